// round 3
// baseline (speedup 1.0000x reference)
#include <cuda_runtime.h>
#include <cstdint>
#include <cstddef>

// Problem constants
#define BB 4096
#define SS 128
#define DD 256
#define CC 5

#define ROWS 32          // batch rows per CTA
#define NTHREADS 256     // 8 warps: warp w owns rows w*4..w*4+3; lane owns 8 j-columns
#define NGRID (BB / ROWS) // 128 CTAs

// Transposed weights + fused bias live in device globals (no allocation allowed).
// __align__(16): read with 128-bit vector loads.
__device__ __align__(16) float g_Wt_ih[DD * DD];   // Wt_ih[k][j] = W_ih[j][k]
__device__ __align__(16) float g_Wt_hh[DD * DD];   // Wt_hh[k][j] = W_hh[j][k]
__device__ __align__(16) float g_bias[DD];         // b_ih + b_hh

// ---------- f32x2 packed-FMA helpers (sm_103a) ----------
__device__ __forceinline__ unsigned long long pack2(float x, float y) {
    unsigned long long r;
    asm("mov.b64 %0, {%1,%2};" : "=l"(r) : "f"(x), "f"(y));
    return r;
}
__device__ __forceinline__ void fma2(unsigned long long& d, unsigned long long a, unsigned long long b) {
    asm("fma.rn.f32x2 %0, %1, %2, %0;" : "+l"(d) : "l"(a), "l"(b));
}
__device__ __forceinline__ float2 unpack2(unsigned long long v) {
    float2 r;
    asm("mov.b64 {%0,%1}, %2;" : "=f"(r.x), "=f"(r.y) : "l"(v));
    return r;
}

// ---------- prep: transpose weights, fuse biases ----------
__global__ void prep_kernel(const float* __restrict__ W_ih,
                            const float* __restrict__ W_hh,
                            const float* __restrict__ b_ih,
                            const float* __restrict__ b_hh) {
    int k = blockIdx.x;   // 0..255
    int j = threadIdx.x;  // 0..255
    g_Wt_ih[k * DD + j] = W_ih[j * DD + k];
    g_Wt_hh[k * DD + j] = W_hh[j * DD + k];
    if (k == 0) g_bias[j] = b_ih[j] + b_hh[j];
}

// ---------- fused persistent RNN kernel ----------
// SMEM layout (floats):
//   xe_s  [ROWS][DD]   gathered embedding tile for current timestep (r-major)
//   h_s   [DD][ROWS]   hidden state, k-major so GEMM2 reads are LDS.128 broadcasts
//   tok_s [ROWS][SS]   (int) all tokens for this CTA's rows, loaded once
#define SMEM_FLOATS (ROWS * DD + DD * ROWS + ROWS * SS)
#define SMEM_BYTES (SMEM_FLOATS * 4)

__global__ void __launch_bounds__(NTHREADS, 1)
rnn_kernel(const int* __restrict__ x,          // NOTE: int32! JAX x64-disabled downcasts int64->int32
           const float* __restrict__ emb,
           const float* __restrict__ W_cls,
           const float* __restrict__ b_cls,
           float* __restrict__ out) {
    extern __shared__ float smem[];
    float* xe_s = smem;                       // ROWS*DD
    float* h_s  = smem + ROWS * DD;           // DD*ROWS
    int*   tok_s = (int*)(smem + 2 * ROWS * DD); // ROWS*SS

    const int tid  = threadIdx.x;
    const int lane = tid & 31;
    const int warp = tid >> 5;
    const int row0 = blockIdx.x * ROWS;

    // thread tile: 4 rows (by warp) x 8 j-columns (by lane)
    const int r0 = warp * 4;
    const int j0 = lane * 8;

    // ---- one-time init: tokens + zero hidden state ----
    for (int idx = tid; idx < ROWS * SS; idx += NTHREADS) {
        int r = idx >> 7;          // / SS
        int t = idx & (SS - 1);
        tok_s[idx] = x[(size_t)(row0 + r) * SS + t];
    }
    for (int idx = tid; idx < DD * ROWS; idx += NTHREADS) h_s[idx] = 0.0f;

    // bias pairs for accumulator init
    const float4 bv0 = *(const float4*)(g_bias + j0);
    const float4 bv1 = *(const float4*)(g_bias + j0 + 4);
    const unsigned long long bp0 = pack2(bv0.x, bv0.y);
    const unsigned long long bp1 = pack2(bv0.z, bv0.w);
    const unsigned long long bp2 = pack2(bv1.x, bv1.y);
    const unsigned long long bp3 = pack2(bv1.z, bv1.w);

    // gather indexing: each warp serves its own 4 rows, 8 lanes per row
    const int g_rloc = warp * 4 + (lane >> 3);
    const int g_sub  = lane & 7;

    __syncthreads();

    for (int t = 0; t < SS; t++) {
        // ---- gather xe(t): 32 rows x 256 floats ----
        {
            int tok = tok_s[g_rloc * SS + t];
            const float* erow = emb + (size_t)tok * DD;
            float* xrow = xe_s + (g_rloc << 8);
            #pragma unroll
            for (int i = 0; i < 8; i++) {
                int col = i * 32 + g_sub * 4;
                *(float4*)(xrow + col) = *(const float4*)(erow + col);
            }
        }
        __syncthreads();   // xe ready; also orders prev-step h writes before GEMM2 reads

        // ---- accumulators: pre = bias + xe@Wih^T + h@Whh^T ----
        unsigned long long acc[4][4];
        #pragma unroll
        for (int rr = 0; rr < 4; rr++) {
            acc[rr][0] = bp0; acc[rr][1] = bp1; acc[rr][2] = bp2; acc[rr][3] = bp3;
        }

        // GEMM1: xe (r-major, scalar broadcast reads) x Wt_ih
        #pragma unroll 4
        for (int k = 0; k < DD; k++) {
            const float* wrow = g_Wt_ih + (k << 8) + j0;
            float4 wa = *(const float4*)(wrow);
            float4 wb = *(const float4*)(wrow + 4);
            unsigned long long w0 = pack2(wa.x, wa.y);
            unsigned long long w1 = pack2(wa.z, wa.w);
            unsigned long long w2 = pack2(wb.x, wb.y);
            unsigned long long w3 = pack2(wb.z, wb.w);
            #pragma unroll
            for (int rr = 0; rr < 4; rr++) {
                float hv = xe_s[((r0 + rr) << 8) + k];
                unsigned long long a = pack2(hv, hv);
                fma2(acc[rr][0], a, w0);
                fma2(acc[rr][1], a, w1);
                fma2(acc[rr][2], a, w2);
                fma2(acc[rr][3], a, w3);
            }
        }

        // GEMM2: h (k-major, LDS.128 broadcast) x Wt_hh
        #pragma unroll 4
        for (int k = 0; k < DD; k++) {
            const float* wrow = g_Wt_hh + (k << 8) + j0;
            float4 wa = *(const float4*)(wrow);
            float4 wb = *(const float4*)(wrow + 4);
            unsigned long long w0 = pack2(wa.x, wa.y);
            unsigned long long w1 = pack2(wa.z, wa.w);
            unsigned long long w2 = pack2(wb.x, wb.y);
            unsigned long long w3 = pack2(wb.z, wb.w);
            float4 hv = *(const float4*)(h_s + k * ROWS + r0);
            unsigned long long a0 = pack2(hv.x, hv.x);
            unsigned long long a1 = pack2(hv.y, hv.y);
            unsigned long long a2 = pack2(hv.z, hv.z);
            unsigned long long a3 = pack2(hv.w, hv.w);
            fma2(acc[0][0], a0, w0); fma2(acc[0][1], a0, w1);
            fma2(acc[0][2], a0, w2); fma2(acc[0][3], a0, w3);
            fma2(acc[1][0], a1, w0); fma2(acc[1][1], a1, w1);
            fma2(acc[1][2], a1, w2); fma2(acc[1][3], a1, w3);
            fma2(acc[2][0], a2, w0); fma2(acc[2][1], a2, w1);
            fma2(acc[2][2], a2, w2); fma2(acc[2][3], a2, w3);
            fma2(acc[3][0], a3, w0); fma2(acc[3][1], a3, w1);
            fma2(acc[3][2], a3, w2); fma2(acc[3][3], a3, w3);
        }

        __syncthreads();   // everyone done READING h_s / xe_s

        // ---- tanh + write new h (k-major): 8 STS.128 per thread ----
        float hout[4][8];
        #pragma unroll
        for (int rr = 0; rr < 4; rr++) {
            #pragma unroll
            for (int p = 0; p < 4; p++) {
                float2 v = unpack2(acc[rr][p]);
                hout[rr][2 * p]     = tanhf(v.x);
                hout[rr][2 * p + 1] = tanhf(v.y);
            }
        }
        #pragma unroll
        for (int jj = 0; jj < 8; jj++) {
            float4 o = make_float4(hout[0][jj], hout[1][jj], hout[2][jj], hout[3][jj]);
            *(float4*)(h_s + (j0 + jj) * ROWS + r0) = o;
        }
        // next iteration's post-gather __syncthreads orders these writes vs reads
    }

    __syncthreads();

    // ---- classifier: out[r][c] = b_cls[c] + sum_d h[r][d] * W_cls[c][d] ----
    if (tid < ROWS * CC) {
        int r = tid / CC;
        int c = tid % CC;
        float s = b_cls[c];
        const float* wc = W_cls + c * DD;
        #pragma unroll 8
        for (int d = 0; d < DD; d++) {
            s += h_s[d * ROWS + r] * wc[d];
        }
        out[(size_t)(row0 + r) * CC + c] = s;
    }
}

extern "C" void kernel_launch(void* const* d_in, const int* in_sizes, int n_in,
                              void* d_out, int out_size) {
    const int* x         = (const int*)d_in[0];   // int32 (JAX default x64-disabled)
    const float* emb     = (const float*)d_in[1];
    const float* W_ih    = (const float*)d_in[2];
    const float* W_hh    = (const float*)d_in[3];
    const float* b_ih    = (const float*)d_in[4];
    const float* b_hh    = (const float*)d_in[5];
    const float* W_cls   = (const float*)d_in[6];
    const float* b_cls   = (const float*)d_in[7];
    float* out = (float*)d_out;

    (void)in_sizes; (void)n_in; (void)out_size;

    cudaFuncSetAttribute(rnn_kernel, cudaFuncAttributeMaxDynamicSharedMemorySize, SMEM_BYTES);

    prep_kernel<<<DD, DD>>>(W_ih, W_hh, b_ih, b_hh);
    rnn_kernel<<<NGRID, NTHREADS, SMEM_BYTES>>>(x, emb, W_cls, b_cls, out);
}

// round 4
// speedup vs baseline: 1.1160x; 1.1160x over previous
#include <cuda_runtime.h>
#include <cstdint>
#include <cstddef>

// Problem constants
#define BB 4096
#define SS 128
#define DD 256
#define CC 5

#define ROWS 32            // batch rows per CTA
#define NTHREADS 256       // 8 warps = 4 row-groups x 2 j-halves
#define NGRID (BB / ROWS)  // 128 CTAs
#define HS 36              // padded stride (floats) of k-major SMEM tiles

// Transposed weights + fused bias (device globals; no runtime allocation allowed).
__device__ __align__(16) float g_Wt_ih[DD * DD];   // Wt_ih[k][j] = W_ih[j][k]
__device__ __align__(16) float g_Wt_hh[DD * DD];   // Wt_hh[k][j] = W_hh[j][k]
__device__ __align__(16) float g_bias[DD];         // b_ih + b_hh

// ---------- f32x2 packed-FMA helpers (sm_103a) ----------
__device__ __forceinline__ unsigned long long pack2(float x, float y) {
    unsigned long long r;
    asm("mov.b64 %0, {%1,%2};" : "=l"(r) : "f"(x), "f"(y));
    return r;
}
__device__ __forceinline__ void fma2(unsigned long long& d, unsigned long long a, unsigned long long b) {
    asm("fma.rn.f32x2 %0, %1, %2, %0;" : "+l"(d) : "l"(a), "l"(b));
}
__device__ __forceinline__ float2 unpack2(unsigned long long v) {
    float2 r;
    asm("mov.b64 {%0,%1}, %2;" : "=f"(r.x), "=f"(r.y) : "l"(v));
    return r;
}

// ---------- prep: transpose weights, fuse biases ----------
__global__ void prep_kernel(const float* __restrict__ W_ih,
                            const float* __restrict__ W_hh,
                            const float* __restrict__ b_ih,
                            const float* __restrict__ b_hh) {
    int k = blockIdx.x;   // 0..255
    int j = threadIdx.x;  // 0..255
    g_Wt_ih[k * DD + j] = W_ih[j * DD + k];
    g_Wt_hh[k * DD + j] = W_hh[j * DD + k];
    if (k == 0) g_bias[j] = b_ih[j] + b_hh[j];
}

// ---------- fused persistent RNN kernel ----------
// SMEM (floats):
//   xe_s [DD][HS]  k-major embedding tile (rows 0..31 + pad)
//   h_s  [DD][HS]  k-major hidden state
//   tok  [ROWS][SS] int tokens, loaded once
#define SMEM_FLOATS (DD * HS * 2 + ROWS * SS)
#define SMEM_BYTES  (SMEM_FLOATS * 4)

__global__ void __launch_bounds__(NTHREADS, 1)
rnn_kernel(const int* __restrict__ x,          // int32 (JAX x64-disabled)
           const float* __restrict__ emb,
           const float* __restrict__ W_cls,
           const float* __restrict__ b_cls,
           float* __restrict__ out) {
    extern __shared__ float smem[];
    float* xe_s  = smem;                 // DD*HS
    float* h_s   = smem + DD * HS;       // DD*HS
    int*   tok_s = (int*)(smem + 2 * DD * HS); // ROWS*SS

    const int tid  = threadIdx.x;
    const int lane = tid & 31;
    const int warp = tid >> 5;
    const int row0 = blockIdx.x * ROWS;

    // thread tile: 8 rows (4 row-pairs) x 4 cols
    const int r0 = (warp >> 1) * 8;                 // 0,8,16,24
    const int j0 = (warp & 1) * 128 + lane * 4;     // 4-col slice

    // gather mapping: thread serves row (tid>>3), col-chunk (tid&7)
    const int g_row = tid >> 3;
    const int g_sub = tid & 7;

    // ---- one-time init: tokens + zero hidden state ----
    for (int idx = tid; idx < ROWS * SS; idx += NTHREADS) {
        int r = idx >> 7;
        int t = idx & (SS - 1);
        tok_s[idx] = x[(size_t)(row0 + r) * SS + t];
    }
    for (int idx = tid; idx < DD * HS; idx += NTHREADS) h_s[idx] = 0.0f;

    // bias pairs: acc pair = (row r, row r+1) of SAME col -> (b[j], b[j])
    const float4 b4 = *(const float4*)(g_bias + j0);
    unsigned long long bp[4];
    bp[0] = pack2(b4.x, b4.x);
    bp[1] = pack2(b4.y, b4.y);
    bp[2] = pack2(b4.z, b4.z);
    bp[3] = pack2(b4.w, b4.w);

    __syncthreads();

    for (int t = 0; t < SS; t++) {
        // ---- gather xe(t) into k-major tile ----
        {
            int tok = tok_s[g_row * SS + t];
            const float* erow = emb + (size_t)tok * DD;
            #pragma unroll
            for (int i = 0; i < 8; i++) {
                int c0 = i * 32 + g_sub * 4;
                float4 v = *(const float4*)(erow + c0);
                xe_s[(c0 + 0) * HS + g_row] = v.x;
                xe_s[(c0 + 1) * HS + g_row] = v.y;
                xe_s[(c0 + 2) * HS + g_row] = v.z;
                xe_s[(c0 + 3) * HS + g_row] = v.w;
            }
        }
        __syncthreads();   // xe ready; also orders prev-step h writes vs GEMM2 reads

        // ---- acc[p][c]: row-pair p (r0+2p, r0+2p+1), col j0+c ----
        unsigned long long acc[4][4];
        #pragma unroll
        for (int p = 0; p < 4; p++) {
            acc[p][0] = bp[0]; acc[p][1] = bp[1]; acc[p][2] = bp[2]; acc[p][3] = bp[3];
        }

        // GEMM1: xe-tile @ Wt_ih
        #pragma unroll 4
        for (int k = 0; k < DD; k++) {
            float4 w = *(const float4*)(g_Wt_ih + (k << 8) + j0);   // 1 LDG.128
            unsigned long long w0 = pack2(w.x, w.x);
            unsigned long long w1 = pack2(w.y, w.y);
            unsigned long long w2 = pack2(w.z, w.z);
            unsigned long long w3 = pack2(w.w, w.w);
            ulonglong2 aA = *(const ulonglong2*)(xe_s + k * HS + r0);     // rows r0..r0+3
            ulonglong2 aB = *(const ulonglong2*)(xe_s + k * HS + r0 + 4); // rows r0+4..r0+7
            fma2(acc[0][0], aA.x, w0); fma2(acc[0][1], aA.x, w1);
            fma2(acc[0][2], aA.x, w2); fma2(acc[0][3], aA.x, w3);
            fma2(acc[1][0], aA.y, w0); fma2(acc[1][1], aA.y, w1);
            fma2(acc[1][2], aA.y, w2); fma2(acc[1][3], aA.y, w3);
            fma2(acc[2][0], aB.x, w0); fma2(acc[2][1], aB.x, w1);
            fma2(acc[2][2], aB.x, w2); fma2(acc[2][3], aB.x, w3);
            fma2(acc[3][0], aB.y, w0); fma2(acc[3][1], aB.y, w1);
            fma2(acc[3][2], aB.y, w2); fma2(acc[3][3], aB.y, w3);
        }

        // GEMM2: h-tile @ Wt_hh
        #pragma unroll 4
        for (int k = 0; k < DD; k++) {
            float4 w = *(const float4*)(g_Wt_hh + (k << 8) + j0);
            unsigned long long w0 = pack2(w.x, w.x);
            unsigned long long w1 = pack2(w.y, w.y);
            unsigned long long w2 = pack2(w.z, w.z);
            unsigned long long w3 = pack2(w.w, w.w);
            ulonglong2 aA = *(const ulonglong2*)(h_s + k * HS + r0);
            ulonglong2 aB = *(const ulonglong2*)(h_s + k * HS + r0 + 4);
            fma2(acc[0][0], aA.x, w0); fma2(acc[0][1], aA.x, w1);
            fma2(acc[0][2], aA.x, w2); fma2(acc[0][3], aA.x, w3);
            fma2(acc[1][0], aA.y, w0); fma2(acc[1][1], aA.y, w1);
            fma2(acc[1][2], aA.y, w2); fma2(acc[1][3], aA.y, w3);
            fma2(acc[2][0], aB.x, w0); fma2(acc[2][1], aB.x, w1);
            fma2(acc[2][2], aB.x, w2); fma2(acc[2][3], aB.x, w3);
            fma2(acc[3][0], aB.y, w0); fma2(acc[3][1], aB.y, w1);
            fma2(acc[3][2], aB.y, w2); fma2(acc[3][3], aB.y, w3);
        }

        __syncthreads();   // all reads of xe_s / h_s complete

        // ---- tanh + write new h (k-major): 2 STS.128 per col ----
        #pragma unroll
        for (int c = 0; c < 4; c++) {
            float hv[8];
            #pragma unroll
            for (int p = 0; p < 4; p++) {
                float2 v = unpack2(acc[p][c]);
                hv[2 * p]     = tanhf(v.x);
                hv[2 * p + 1] = tanhf(v.y);
            }
            float* dst = h_s + (j0 + c) * HS + r0;
            *(float4*)(dst)     = make_float4(hv[0], hv[1], hv[2], hv[3]);
            *(float4*)(dst + 4) = make_float4(hv[4], hv[5], hv[6], hv[7]);
        }
        // next iteration's post-gather barrier orders these writes vs reads
    }

    __syncthreads();

    // ---- classifier: out[r][c] = b_cls[c] + sum_d h[r][d] * W_cls[c][d] ----
    if (tid < ROWS * CC) {
        int r = tid / CC;
        int c = tid % CC;
        float s = b_cls[c];
        const float* wc = W_cls + c * DD;
        #pragma unroll 8
        for (int d = 0; d < DD; d++) {
            s += h_s[d * HS + r] * wc[d];
        }
        out[(size_t)(row0 + r) * CC + c] = s;
    }
}

extern "C" void kernel_launch(void* const* d_in, const int* in_sizes, int n_in,
                              void* d_out, int out_size) {
    const int* x         = (const int*)d_in[0];   // int32
    const float* emb     = (const float*)d_in[1];
    const float* W_ih    = (const float*)d_in[2];
    const float* W_hh    = (const float*)d_in[3];
    const float* b_ih    = (const float*)d_in[4];
    const float* b_hh    = (const float*)d_in[5];
    const float* W_cls   = (const float*)d_in[6];
    const float* b_cls   = (const float*)d_in[7];
    float* out = (float*)d_out;

    (void)in_sizes; (void)n_in; (void)out_size;

    cudaFuncSetAttribute(rnn_kernel, cudaFuncAttributeMaxDynamicSharedMemorySize, SMEM_BYTES);

    prep_kernel<<<DD, DD>>>(W_ih, W_hh, b_ih, b_hh);
    rnn_kernel<<<NGRID, NTHREADS, SMEM_BYTES>>>(x, emb, W_cls, b_cls, out);
}

// round 5
// speedup vs baseline: 1.5067x; 1.3501x over previous
#include <cuda_runtime.h>
#include <cstdint>
#include <cstddef>

// Problem constants
#define BB 4096
#define SS 128
#define DD 256
#define CC 5

#define ROWS 32            // batch rows per CTA
#define NTHREADS 512       // 16 warps = 8 row-groups (4 rows) x 2 j-halves (128 cols)
#define NGRID (BB / ROWS)  // 128 CTAs
#define HS 36              // padded stride (floats) of k-major SMEM tiles
#define KK (2 * DD)        // fused K dimension: [xe ; h]

// Fused transposed weights [512][256]: rows 0..255 = W_ih^T, rows 256..511 = W_hh^T.
__device__ __align__(16) float g_W[KK * DD];
__device__ __align__(16) float g_bias[DD];   // b_ih + b_hh

// ---------- f32x2 packed-FMA helpers (sm_103a) ----------
__device__ __forceinline__ unsigned long long pack2(float x, float y) {
    unsigned long long r;
    asm("mov.b64 %0, {%1,%2};" : "=l"(r) : "f"(x), "f"(y));
    return r;
}
__device__ __forceinline__ void fma2(unsigned long long& d, unsigned long long a, unsigned long long b) {
    asm("fma.rn.f32x2 %0, %1, %2, %0;" : "+l"(d) : "l"(a), "l"(b));
}
__device__ __forceinline__ float2 unpack2(unsigned long long v) {
    float2 r;
    asm("mov.b64 {%0,%1}, %2;" : "=f"(r.x), "=f"(r.y) : "l"(v));
    return r;
}

// ---------- prep: transpose+concat weights, fuse biases ----------
__global__ void prep_kernel(const float* __restrict__ W_ih,
                            const float* __restrict__ W_hh,
                            const float* __restrict__ b_ih,
                            const float* __restrict__ b_hh) {
    int k = blockIdx.x;   // 0..511
    int j = threadIdx.x;  // 0..255
    if (k < DD) g_W[k * DD + j] = W_ih[j * DD + k];
    else        g_W[k * DD + j] = W_hh[j * DD + (k - DD)];
    if (k == 0) g_bias[j] = b_ih[j] + b_hh[j];
}

// ---------- fused persistent RNN kernel ----------
// SMEM (floats):
//   ab_s [KK][HS]  k-major fused tile: rows 0..255 = xe(t), rows 256..511 = h(t)
//   tok  [ROWS][SS] int tokens, loaded once
#define SMEM_FLOATS (KK * HS + ROWS * SS)
#define SMEM_BYTES  (SMEM_FLOATS * 4)

__global__ void __launch_bounds__(NTHREADS, 1)
rnn_kernel(const int* __restrict__ x,          // int32 (JAX x64-disabled)
           const float* __restrict__ emb,
           const float* __restrict__ W_cls,
           const float* __restrict__ b_cls,
           float* __restrict__ out) {
    extern __shared__ float smem[];
    float* ab_s  = smem;                       // KK*HS  (xe rows 0..255, h rows 256..511)
    int*   tok_s = (int*)(smem + KK * HS);     // ROWS*SS

    const int tid  = threadIdx.x;
    const int lane = tid & 31;
    const int warp = tid >> 5;
    const int row0 = blockIdx.x * ROWS;

    // warp tile: 4 rows x 128 cols; thread tile: 4 rows x 4 cols
    const int r0 = (warp >> 1) * 4;                  // 0,4,...,28
    const int j0 = (warp & 1) * 128 + lane * 4;

    // gather mapping: 16 threads per row, 4 float4 chunks each
    const int g_row = tid >> 4;     // 0..31
    const int g_sub = tid & 15;

    // ---- one-time init: tokens + zero hidden region ----
    for (int idx = tid; idx < ROWS * SS; idx += NTHREADS) {
        int r = idx >> 7;
        int t = idx & (SS - 1);
        tok_s[idx] = x[(size_t)(row0 + r) * SS + t];
    }
    for (int idx = tid; idx < DD * HS; idx += NTHREADS) ab_s[DD * HS + idx] = 0.0f;

    // bias pairs: acc pair = (row, row+1) of SAME col -> (b[j], b[j])
    const float4 b4 = *(const float4*)(g_bias + j0);
    unsigned long long bp[4];
    bp[0] = pack2(b4.x, b4.x);
    bp[1] = pack2(b4.y, b4.y);
    bp[2] = pack2(b4.z, b4.z);
    bp[3] = pack2(b4.w, b4.w);

    __syncthreads();   // tok_s + h-zero visible

    // ---- prologue: gather xe(0) into regs, commit to SMEM ----
    float4 xr[4];
    {
        int tok = tok_s[g_row * SS + 0];
        const float* erow = emb + (size_t)tok * DD;
        #pragma unroll
        for (int i = 0; i < 4; i++) xr[i] = *(const float4*)(erow + i * 64 + g_sub * 4);
    }
    #pragma unroll
    for (int i = 0; i < 4; i++) {
        int c0 = i * 64 + g_sub * 4;
        ab_s[(c0 + 0) * HS + g_row] = xr[i].x;
        ab_s[(c0 + 1) * HS + g_row] = xr[i].y;
        ab_s[(c0 + 2) * HS + g_row] = xr[i].z;
        ab_s[(c0 + 3) * HS + g_row] = xr[i].w;
    }
    __syncthreads();

    for (int t = 0; t < SS; t++) {
        // ---- prefetch xe(t+1) into regs (overlaps with GEMM below) ----
        {
            int tn = (t + 1 < SS) ? (t + 1) : t;
            int tok = tok_s[g_row * SS + tn];
            const float* erow = emb + (size_t)tok * DD;
            #pragma unroll
            for (int i = 0; i < 4; i++) xr[i] = *(const float4*)(erow + i * 64 + g_sub * 4);
        }

        // ---- fused GEMM: pre = bias + [xe;h] @ [Wt_ih;Wt_hh] ----
        unsigned long long acc[2][4];
        acc[0][0] = bp[0]; acc[0][1] = bp[1]; acc[0][2] = bp[2]; acc[0][3] = bp[3];
        acc[1][0] = bp[0]; acc[1][1] = bp[1]; acc[1][2] = bp[2]; acc[1][3] = bp[3];

        #pragma unroll 8
        for (int k = 0; k < KK; k++) {
            float4 w = *(const float4*)(g_W + (k << 8) + j0);        // 1 LDG.128
            ulonglong2 a = *(const ulonglong2*)(ab_s + k * HS + r0); // LDS.128 broadcast: rows r0..r0+3
            unsigned long long w0 = pack2(w.x, w.x);
            unsigned long long w1 = pack2(w.y, w.y);
            unsigned long long w2 = pack2(w.z, w.z);
            unsigned long long w3 = pack2(w.w, w.w);
            fma2(acc[0][0], a.x, w0); fma2(acc[0][1], a.x, w1);
            fma2(acc[0][2], a.x, w2); fma2(acc[0][3], a.x, w3);
            fma2(acc[1][0], a.y, w0); fma2(acc[1][1], a.y, w1);
            fma2(acc[1][2], a.y, w2); fma2(acc[1][3], a.y, w3);
        }

        // ---- tanh (register-only, before the barrier) ----
        float hv[4][4];   // hv[c][rr] : col c, rows r0..r0+3
        #pragma unroll
        for (int c = 0; c < 4; c++) {
            float2 v0 = unpack2(acc[0][c]);
            float2 v1 = unpack2(acc[1][c]);
            hv[c][0] = tanhf(v0.x);
            hv[c][1] = tanhf(v0.y);
            hv[c][2] = tanhf(v1.x);
            hv[c][3] = tanhf(v1.y);
        }

        __syncthreads();   // all reads of ab_s (xe & h) complete

        // ---- commit new h (k-major) + xe(t+1) ----
        #pragma unroll
        for (int c = 0; c < 4; c++) {
            *(float4*)(ab_s + (DD + j0 + c) * HS + r0) =
                make_float4(hv[c][0], hv[c][1], hv[c][2], hv[c][3]);
        }
        #pragma unroll
        for (int i = 0; i < 4; i++) {
            int c0 = i * 64 + g_sub * 4;
            ab_s[(c0 + 0) * HS + g_row] = xr[i].x;
            ab_s[(c0 + 1) * HS + g_row] = xr[i].y;
            ab_s[(c0 + 2) * HS + g_row] = xr[i].z;
            ab_s[(c0 + 3) * HS + g_row] = xr[i].w;
        }
        __syncthreads();   // writes visible for next step
    }

    // ---- classifier: out[r][c] = b_cls[c] + sum_d h[r][d] * W_cls[c][d] ----
    if (tid < ROWS * CC) {
        int r = tid / CC;
        int c = tid % CC;
        float s = b_cls[c];
        const float* wc = W_cls + c * DD;
        #pragma unroll 8
        for (int d = 0; d < DD; d++) {
            s += ab_s[(DD + d) * HS + r] * wc[d];
        }
        out[(size_t)(row0 + r) * CC + c] = s;
    }
}

extern "C" void kernel_launch(void* const* d_in, const int* in_sizes, int n_in,
                              void* d_out, int out_size) {
    const int* x         = (const int*)d_in[0];   // int32
    const float* emb     = (const float*)d_in[1];
    const float* W_ih    = (const float*)d_in[2];
    const float* W_hh    = (const float*)d_in[3];
    const float* b_ih    = (const float*)d_in[4];
    const float* b_hh    = (const float*)d_in[5];
    const float* W_cls   = (const float*)d_in[6];
    const float* b_cls   = (const float*)d_in[7];
    float* out = (float*)d_out;

    (void)in_sizes; (void)n_in; (void)out_size;

    cudaFuncSetAttribute(rnn_kernel, cudaFuncAttributeMaxDynamicSharedMemorySize, SMEM_BYTES);

    prep_kernel<<<KK, DD>>>(W_ih, W_hh, b_ih, b_hh);
    rnn_kernel<<<NGRID, NTHREADS, SMEM_BYTES>>>(x, emb, W_cls, b_cls, out);
}

// round 6
// speedup vs baseline: 1.5106x; 1.0026x over previous
#include <cuda_runtime.h>
#include <cstdint>
#include <cstddef>

// Problem constants
#define BB 4096
#define SS 128
#define DD 256
#define CC 5

#define ROWS 32            // batch rows per CTA
#define NTHREADS 512       // 16 warps = 8 row-groups (4 rows) x 2 j-halves (128 cols)
#define NGRID (BB / ROWS)  // 128 CTAs
#define HS 36              // padded stride (floats) of k-major SMEM tiles
#define KK (2 * DD)        // fused K dimension: [xe ; h]

// Fused transposed weights [512][256]: rows 0..255 = W_ih^T, rows 256..511 = W_hh^T.
__device__ __align__(16) float g_W[KK * DD];
__device__ __align__(16) float g_bias[DD];   // b_ih + b_hh

// ---------- f32x2 packed-FMA helpers (sm_103a) ----------
__device__ __forceinline__ unsigned long long pack2(float x, float y) {
    unsigned long long r;
    asm("mov.b64 %0, {%1,%2};" : "=l"(r) : "f"(x), "f"(y));
    return r;
}
__device__ __forceinline__ void fma2(unsigned long long& d, unsigned long long a, unsigned long long b) {
    asm("fma.rn.f32x2 %0, %1, %2, %0;" : "+l"(d) : "l"(a), "l"(b));
}
__device__ __forceinline__ float2 unpack2(unsigned long long v) {
    float2 r;
    asm("mov.b64 {%0,%1}, %2;" : "=f"(r.x), "=f"(r.y) : "l"(v));
    return r;
}

// ---------- prep: transpose+concat weights, fuse biases ----------
__global__ void prep_kernel(const float* __restrict__ W_ih,
                            const float* __restrict__ W_hh,
                            const float* __restrict__ b_ih,
                            const float* __restrict__ b_hh) {
    int k = blockIdx.x;   // 0..511
    int j = threadIdx.x;  // 0..255
    if (k < DD) g_W[k * DD + j] = W_ih[j * DD + k];
    else        g_W[k * DD + j] = W_hh[j * DD + (k - DD)];
    if (k == 0) g_bias[j] = b_ih[j] + b_hh[j];
}

// ---------- fused persistent RNN kernel ----------
// SMEM (floats):
//   ab_s [KK][HS]  k-major fused tile: rows 0..255 = xe(t), rows 256..511 = h(t)
//   tok  [ROWS][SS] int tokens, loaded once
#define SMEM_FLOATS (KK * HS + ROWS * SS)
#define SMEM_BYTES  (SMEM_FLOATS * 4)

__global__ void __launch_bounds__(NTHREADS, 1)
rnn_kernel(const int* __restrict__ x,          // int32 (JAX x64-disabled)
           const float* __restrict__ emb,
           const float* __restrict__ W_cls,
           const float* __restrict__ b_cls,
           float* __restrict__ out) {
    extern __shared__ float smem[];
    float* ab_s  = smem;                       // KK*HS  (xe rows 0..255, h rows 256..511)
    int*   tok_s = (int*)(smem + KK * HS);     // ROWS*SS

    const int tid  = threadIdx.x;
    const int lane = tid & 31;
    const int warp = tid >> 5;
    const int row0 = blockIdx.x * ROWS;

    // warp tile: 4 rows x 128 cols; thread tile: 4 rows x 4 cols
    const int r0 = (warp >> 1) * 4;                  // 0,4,...,28
    const int j0 = (warp & 1) * 128 + lane * 4;

    // gather mapping: 16 threads per row, 4 float4 chunks each
    const int g_row = tid >> 4;     // 0..31
    const int g_sub = tid & 15;

    // ---- one-time init: tokens + zero hidden region ----
    for (int idx = tid; idx < ROWS * SS; idx += NTHREADS) {
        int r = idx >> 7;
        int t = idx & (SS - 1);
        tok_s[idx] = x[(size_t)(row0 + r) * SS + t];
    }
    for (int idx = tid; idx < DD * HS; idx += NTHREADS) ab_s[DD * HS + idx] = 0.0f;

    // bias pairs: acc pair = (row, row+1) of SAME col -> (b[j], b[j])
    const float4 b4 = *(const float4*)(g_bias + j0);
    unsigned long long bp[4];
    bp[0] = pack2(b4.x, b4.x);
    bp[1] = pack2(b4.y, b4.y);
    bp[2] = pack2(b4.z, b4.z);
    bp[3] = pack2(b4.w, b4.w);

    __syncthreads();   // tok_s + h-zero visible

    // ---- prologue: gather xe(0) into regs, commit to SMEM ----
    float4 xr[4];
    {
        int tok = tok_s[g_row * SS + 0];
        const float* erow = emb + (size_t)tok * DD;
        #pragma unroll
        for (int i = 0; i < 4; i++) xr[i] = *(const float4*)(erow + i * 64 + g_sub * 4);
    }
    #pragma unroll
    for (int i = 0; i < 4; i++) {
        int c0 = i * 64 + g_sub * 4;
        ab_s[(c0 + 0) * HS + g_row] = xr[i].x;
        ab_s[(c0 + 1) * HS + g_row] = xr[i].y;
        ab_s[(c0 + 2) * HS + g_row] = xr[i].z;
        ab_s[(c0 + 3) * HS + g_row] = xr[i].w;
    }
    __syncthreads();

    for (int t = 0; t < SS; t++) {
        // ---- prefetch xe(t+1) into regs (overlaps with GEMM below) ----
        {
            int tn = (t + 1 < SS) ? (t + 1) : t;
            int tok = tok_s[g_row * SS + tn];
            const float* erow = emb + (size_t)tok * DD;
            #pragma unroll
            for (int i = 0; i < 4; i++) xr[i] = *(const float4*)(erow + i * 64 + g_sub * 4);
        }

        // ---- fused GEMM: pre = bias + [xe;h] @ [Wt_ih;Wt_hh] ----
        unsigned long long acc[2][4];
        acc[0][0] = bp[0]; acc[0][1] = bp[1]; acc[0][2] = bp[2]; acc[0][3] = bp[3];
        acc[1][0] = bp[0]; acc[1][1] = bp[1]; acc[1][2] = bp[2]; acc[1][3] = bp[3];

        #pragma unroll 8
        for (int k = 0; k < KK; k++) {
            float4 w = *(const float4*)(g_W + (k << 8) + j0);        // 1 LDG.128
            ulonglong2 a = *(const ulonglong2*)(ab_s + k * HS + r0); // LDS.128 broadcast: rows r0..r0+3
            unsigned long long w0 = pack2(w.x, w.x);
            unsigned long long w1 = pack2(w.y, w.y);
            unsigned long long w2 = pack2(w.z, w.z);
            unsigned long long w3 = pack2(w.w, w.w);
            fma2(acc[0][0], a.x, w0); fma2(acc[0][1], a.x, w1);
            fma2(acc[0][2], a.x, w2); fma2(acc[0][3], a.x, w3);
            fma2(acc[1][0], a.y, w0); fma2(acc[1][1], a.y, w1);
            fma2(acc[1][2], a.y, w2); fma2(acc[1][3], a.y, w3);
        }

        // ---- tanh (register-only, before the barrier) ----
        float hv[4][4];   // hv[c][rr] : col c, rows r0..r0+3
        #pragma unroll
        for (int c = 0; c < 4; c++) {
            float2 v0 = unpack2(acc[0][c]);
            float2 v1 = unpack2(acc[1][c]);
            hv[c][0] = tanhf(v0.x);
            hv[c][1] = tanhf(v0.y);
            hv[c][2] = tanhf(v1.x);
            hv[c][3] = tanhf(v1.y);
        }

        __syncthreads();   // all reads of ab_s (xe & h) complete

        // ---- commit new h (k-major) + xe(t+1) ----
        #pragma unroll
        for (int c = 0; c < 4; c++) {
            *(float4*)(ab_s + (DD + j0 + c) * HS + r0) =
                make_float4(hv[c][0], hv[c][1], hv[c][2], hv[c][3]);
        }
        #pragma unroll
        for (int i = 0; i < 4; i++) {
            int c0 = i * 64 + g_sub * 4;
            ab_s[(c0 + 0) * HS + g_row] = xr[i].x;
            ab_s[(c0 + 1) * HS + g_row] = xr[i].y;
            ab_s[(c0 + 2) * HS + g_row] = xr[i].z;
            ab_s[(c0 + 3) * HS + g_row] = xr[i].w;
        }
        __syncthreads();   // writes visible for next step
    }

    // ---- classifier: out[r][c] = b_cls[c] + sum_d h[r][d] * W_cls[c][d] ----
    if (tid < ROWS * CC) {
        int r = tid / CC;
        int c = tid % CC;
        float s = b_cls[c];
        const float* wc = W_cls + c * DD;
        #pragma unroll 8
        for (int d = 0; d < DD; d++) {
            s += ab_s[(DD + d) * HS + r] * wc[d];
        }
        out[(size_t)(row0 + r) * CC + c] = s;
    }
}

extern "C" void kernel_launch(void* const* d_in, const int* in_sizes, int n_in,
                              void* d_out, int out_size) {
    const int* x         = (const int*)d_in[0];   // int32
    const float* emb     = (const float*)d_in[1];
    const float* W_ih    = (const float*)d_in[2];
    const float* W_hh    = (const float*)d_in[3];
    const float* b_ih    = (const float*)d_in[4];
    const float* b_hh    = (const float*)d_in[5];
    const float* W_cls   = (const float*)d_in[6];
    const float* b_cls   = (const float*)d_in[7];
    float* out = (float*)d_out;

    (void)in_sizes; (void)n_in; (void)out_size;

    cudaFuncSetAttribute(rnn_kernel, cudaFuncAttributeMaxDynamicSharedMemorySize, SMEM_BYTES);

    prep_kernel<<<KK, DD>>>(W_ih, W_hh, b_ih, b_hh);
    rnn_kernel<<<NGRID, NTHREADS, SMEM_BYTES>>>(x, emb, W_cls, b_cls, out);
}